// round 1
// baseline (speedup 1.0000x reference)
#include <cuda_runtime.h>
#include <math.h>

#define T_   2048
#define B_   8
#define S_   512
#define D_   512
#define H_   8
#define DH   64
#define DFF_ 2048
#define NQ_  10
#define W_   16
#define NW   128
#define EPS  1e-5f
#define NEGV -1e30f

// ---------------- scratch (no dynamic allocation allowed) ----------------
__device__ float g_qn[NQ_ * D_];
__device__ float g_qa[B_ * NW * D_];
__device__ float g_x1[T_ * B_ * D_];
__device__ float g_q [T_ * B_ * D_];
__device__ float g_kv[S_ * B_ * 2 * D_];
__device__ float g_o [T_ * B_ * D_];
__device__ float g_tmp[T_ * B_ * D_];
__device__ float g_x2[T_ * B_ * D_];
__device__ float g_h [T_ * B_ * DFF_];

// ---------------- query normalization (QaN) ----------------
// qn[n,d] = q[n,d] / ((||q[n,h]||+1e-6) * sqrt(dh)) * D^-0.5   (scale folded in)
__global__ void prep_q_kernel(const float* __restrict__ q) {
    int n = blockIdx.x / H_, h = blockIdx.x % H_;
    int lane = threadIdx.x;
    const float* base = q + n * D_ + h * DH;
    float v0 = base[lane];
    float v1 = base[lane + 32];
    float ss = v0 * v0 + v1 * v1;
    #pragma unroll
    for (int o = 16; o; o >>= 1) ss += __shfl_xor_sync(0xffffffffu, ss, o);
    float f = 1.0f / ((sqrtf(ss) + 1e-6f) * 8.0f * sqrtf(512.0f));
    g_qn[n * D_ + h * DH + lane]      = v0 * f;
    g_qn[n * D_ + h * DH + lane + 32] = v1 * f;
}

// ---------------- QaN local-attention block ----------------
// One block per (b, window m). 48 keys = windows m-1,m,m+1 (masked at edges).
// Output row is identical for all W positions in the window -> write (b,m,:).
__global__ __launch_bounds__(256) void qa_kernel(const float* __restrict__ tgt,
                                                 const float* __restrict__ wk) {
    extern __shared__ float sm[];
    float* kv  = sm;                 // 48*512
    float* qs  = kv + 48 * 512;      // 10*512
    float* sim = qs + 10 * 512;      // 10*48
    float* wj  = sim + 10 * 48;      // 48

    int bx = blockIdx.x;
    int b = bx >> 7, m = bx & 127;
    int tid = threadIdx.x;

    for (int idx = tid; idx < 48 * 512; idx += 256) {
        int j = idx >> 9, d = idx & 511;
        int p = (m - 1) * W_ + j;
        kv[idx] = (p >= 0 && p < T_) ? tgt[(p * B_ + b) * D_ + d] : 0.0f;
    }
    for (int idx = tid; idx < 10 * 512; idx += 256) qs[idx] = g_qn[idx];
    __syncthreads();

    int w = tid >> 5, lane = tid & 31;
    // 480 dot products of length 512
    for (int pw = w; pw < 480; pw += 8) {
        int n = pw / 48, j = pw % 48;
        const float* kr = kv + j * 512;
        const float* qr = qs + n * 512;
        float s = 0.f;
        for (int d = lane; d < 512; d += 32) s += kr[d] * qr[d];
        #pragma unroll
        for (int o = 16; o; o >>= 1) s += __shfl_xor_sync(0xffffffffu, s, o);
        if (lane == 0) {
            int win = m - 1 + (j >> 4);
            sim[n * 48 + j] = (win >= 0 && win < NW) ? s : NEGV;
        }
    }
    __syncthreads();

    // softmax over 48 per query n (warp-per-row)
    for (int n = w; n < NQ_; n += 8) {
        float v0 = sim[n * 48 + lane];                      // lanes 0..31
        float v1 = (lane < 16) ? sim[n * 48 + 32 + lane] : NEGV;
        float mx = fmaxf(v0, v1);
        #pragma unroll
        for (int o = 16; o; o >>= 1) mx = fmaxf(mx, __shfl_xor_sync(0xffffffffu, mx, o));
        float e0 = __expf(v0 - mx);
        float e1 = (lane < 16) ? __expf(v1 - mx) : 0.f;
        float su = e0 + e1;
        #pragma unroll
        for (int o = 16; o; o >>= 1) su += __shfl_xor_sync(0xffffffffu, su, o);
        float inv = 1.0f / su;
        sim[n * 48 + lane] = e0 * inv;
        if (lane < 16) sim[n * 48 + 32 + lane] = e1 * inv;
    }
    __syncthreads();

    // collapse query mix first: wj[j] = sum_n wk[n] * attn[n,j]
    if (tid < 48) {
        float acc = 0.f;
        #pragma unroll
        for (int n = 0; n < NQ_; n++) acc += wk[n] * sim[n * 48 + tid];
        wj[tid] = acc;
    }
    __syncthreads();

    for (int d = tid; d < 512; d += 256) {
        float acc = 0.f;
        #pragma unroll
        for (int j = 0; j < 48; j++) acc += wj[j] * kv[j * 512 + d];
        g_qa[(b * NW + m) * D_ + d] = acc;
    }
}

// ---------------- residual add + LayerNorm ----------------
__device__ __forceinline__ float block_sum(float v, float* red) {
    int lane = threadIdx.x & 31, w = threadIdx.x >> 5;
    __syncthreads();   // protect red reuse
    #pragma unroll
    for (int o = 16; o; o >>= 1) v += __shfl_xor_sync(0xffffffffu, v, o);
    if (lane == 0) red[w] = v;
    __syncthreads();
    v = (lane < 8) ? red[lane] : 0.f;
    #pragma unroll
    for (int o = 4; o; o >>= 1) v += __shfl_xor_sync(0xffffffffu, v, o);
    return __shfl_sync(0xffffffffu, v, 0);
}

// mode 0: b row = r. mode 1: b row = qa[(r%B)*NW + (r/B)/W]
__global__ __launch_bounds__(256) void add_ln_kernel(const float* __restrict__ a,
                                                     const float* __restrict__ bsrc,
                                                     const float* __restrict__ g,
                                                     const float* __restrict__ be,
                                                     float* __restrict__ out, int mode) {
    __shared__ float red[8];
    int r = blockIdx.x, tid = threadIdx.x;
    const float* ar = a + (size_t)r * D_;
    const float* br;
    if (mode == 1) {
        int t = r / B_, b = r % B_;
        br = bsrc + (size_t)(b * NW + (t >> 4)) * D_;
    } else {
        br = bsrc + (size_t)r * D_;
    }
    float x0 = ar[tid]       + br[tid];
    float x1 = ar[tid + 256] + br[tid + 256];
    float mu = block_sum(x0 + x1, red) * (1.0f / 512.0f);
    float d0 = x0 - mu, d1 = x1 - mu;
    float var = block_sum(d0 * d0 + d1 * d1, red) * (1.0f / 512.0f);
    float inv = rsqrtf(var + EPS);
    out[(size_t)r * D_ + tid]       = d0 * inv * g[tid]       + be[tid];
    out[(size_t)r * D_ + tid + 256] = d1 * inv * g[tid + 256] + be[tid + 256];
}

// ---------------- SGEMM: C[M,N] = A[M,K] @ W[N,K]^T + bias (NT form) ----------------
template<int RELU>
__global__ __launch_bounds__(256) void sgemm_nt(const float* __restrict__ A,
                                                const float* __restrict__ Wt,
                                                const float* __restrict__ bias,
                                                float* __restrict__ C,
                                                int M, int N, int K) {
    __shared__ float As[8][128];
    __shared__ float Bs[8][128];
    int m0 = blockIdx.y * 128, n0 = blockIdx.x * 128;
    int t = threadIdx.x;
    int ar = t >> 1, ac = (t & 1) << 2;
    int tr = (t >> 4) << 3, tc = (t & 15) << 3;

    float acc[8][8];
    #pragma unroll
    for (int i = 0; i < 8; i++)
        #pragma unroll
        for (int j = 0; j < 8; j++) acc[i][j] = 0.f;

    const float* Ap = A  + (size_t)(m0 + ar) * K + ac;
    const float* Bp = Wt + (size_t)(n0 + ar) * K + ac;

    for (int k0 = 0; k0 < K; k0 += 8) {
        float4 a4 = *(const float4*)(Ap + k0);
        float4 b4 = *(const float4*)(Bp + k0);
        As[ac + 0][ar] = a4.x; As[ac + 1][ar] = a4.y;
        As[ac + 2][ar] = a4.z; As[ac + 3][ar] = a4.w;
        Bs[ac + 0][ar] = b4.x; Bs[ac + 1][ar] = b4.y;
        Bs[ac + 2][ar] = b4.z; Bs[ac + 3][ar] = b4.w;
        __syncthreads();
        #pragma unroll
        for (int k = 0; k < 8; k++) {
            float ra[8], rb[8];
            *(float4*)(ra)     = *(const float4*)(&As[k][tr]);
            *(float4*)(ra + 4) = *(const float4*)(&As[k][tr + 4]);
            *(float4*)(rb)     = *(const float4*)(&Bs[k][tc]);
            *(float4*)(rb + 4) = *(const float4*)(&Bs[k][tc + 4]);
            #pragma unroll
            for (int i = 0; i < 8; i++)
                #pragma unroll
                for (int j = 0; j < 8; j++) acc[i][j] += ra[i] * rb[j];
        }
        __syncthreads();
    }

    #pragma unroll
    for (int i = 0; i < 8; i++) {
        size_t row = (size_t)(m0 + tr + i) * N + n0 + tc;
        #pragma unroll
        for (int j = 0; j < 8; j += 4) {
            float4 o;
            o.x = acc[i][j + 0] + bias[n0 + tc + j + 0];
            o.y = acc[i][j + 1] + bias[n0 + tc + j + 1];
            o.z = acc[i][j + 2] + bias[n0 + tc + j + 2];
            o.w = acc[i][j + 3] + bias[n0 + tc + j + 3];
            if (RELU) {
                o.x = fmaxf(o.x, 0.f); o.y = fmaxf(o.y, 0.f);
                o.z = fmaxf(o.z, 0.f); o.w = fmaxf(o.w, 0.f);
            }
            *(float4*)(C + row + j) = o;
        }
    }
}

// ---------------- cross attention (B,H) heads, S=512, dh=64 ----------------
#define SROW 513   // padded score row stride (bank-conflict break)
#define ATTN_SMEM ((4096 + 8192 + 64 * SROW) * 4)

__global__ __launch_bounds__(256) void attn_kernel(const float* __restrict__ Q,
                                                   const float* __restrict__ KV,
                                                   float* __restrict__ O) {
    extern __shared__ float sm[];
    float* Qt = sm;            // [64 d][64 i]
    float* Kt = sm + 4096;     // [64 d][128 s]   (reused as Vs[64 s][68 d])
    float* Ss = Kt + 8192;     // [64 i][SROW]

    int qt0 = blockIdx.x * 64, h = blockIdx.y, b = blockIdx.z;
    int tid = threadIdx.x;
    int ti = tid & 15, ts = tid >> 4;

    // load Q tile transposed, scale folded (1/sqrt(64))
    for (int idx = tid; idx < 4096; idx += 256) {
        int i = idx >> 6, d = idx & 63;
        Qt[d * 64 + i] = Q[((size_t)(qt0 + i) * B_ + b) * D_ + h * DH + d] * 0.125f;
    }

    // scores: 64 x 512 = QK^T
    for (int sch = 0; sch < 512; sch += 128) {
        __syncthreads();
        for (int idx = tid; idx < 8192; idx += 256) {
            int s = idx >> 6, d = idx & 63;
            Kt[d * 128 + s] = KV[((size_t)(sch + s) * B_ + b) * (2 * D_) + h * DH + d];
        }
        __syncthreads();
        float acc[4][8];
        #pragma unroll
        for (int a = 0; a < 4; a++)
            #pragma unroll
            for (int j = 0; j < 8; j++) acc[a][j] = 0.f;
        #pragma unroll 4
        for (int d = 0; d < 64; d++) {
            float4 q4 = *(const float4*)(Qt + d * 64 + ti * 4);
            float4 ka = *(const float4*)(Kt + d * 128 + ts * 8);
            float4 kb = *(const float4*)(Kt + d * 128 + ts * 8 + 4);
            float rq[4] = {q4.x, q4.y, q4.z, q4.w};
            float rk[8] = {ka.x, ka.y, ka.z, ka.w, kb.x, kb.y, kb.z, kb.w};
            #pragma unroll
            for (int a = 0; a < 4; a++)
                #pragma unroll
                for (int j = 0; j < 8; j++) acc[a][j] += rq[a] * rk[j];
        }
        #pragma unroll
        for (int a = 0; a < 4; a++)
            #pragma unroll
            for (int j = 0; j < 8; j++)
                Ss[(ti * 4 + a) * SROW + sch + ts * 8 + j] = acc[a][j];
    }
    __syncthreads();

    // softmax (no mask), warp per 8 rows
    int w = tid >> 5, lane = tid & 31;
    for (int i = w * 8; i < w * 8 + 8; i++) {
        float* row = Ss + i * SROW;
        float mx = -INFINITY;
        for (int s = lane; s < 512; s += 32) mx = fmaxf(mx, row[s]);
        #pragma unroll
        for (int o = 16; o; o >>= 1) mx = fmaxf(mx, __shfl_xor_sync(0xffffffffu, mx, o));
        float su = 0.f;
        for (int s = lane; s < 512; s += 32) {
            float e = __expf(row[s] - mx);
            row[s] = e; su += e;
        }
        #pragma unroll
        for (int o = 16; o; o >>= 1) su += __shfl_xor_sync(0xffffffffu, su, o);
        float inv = 1.0f / su;
        for (int s = lane; s < 512; s += 32) row[s] *= inv;
    }

    // O = P @ V   (64 x 64)
    float* Vs = Kt;   // [64 s][68 d]
    int td = ts;
    float oacc[4][4];
    #pragma unroll
    for (int a = 0; a < 4; a++)
        #pragma unroll
        for (int j = 0; j < 4; j++) oacc[a][j] = 0.f;

    for (int sch = 0; sch < 512; sch += 64) {
        __syncthreads();
        for (int idx = tid; idx < 4096; idx += 256) {
            int s = idx >> 6, d = idx & 63;
            Vs[s * 68 + d] = KV[((size_t)(sch + s) * B_ + b) * (2 * D_) + D_ + h * DH + d];
        }
        __syncthreads();
        #pragma unroll 4
        for (int s = 0; s < 64; s++) {
            float4 v4 = *(const float4*)(Vs + s * 68 + td * 4);
            #pragma unroll
            for (int a = 0; a < 4; a++) {
                float p = Ss[(ti + 16 * a) * SROW + sch + s];
                oacc[a][0] += p * v4.x; oacc[a][1] += p * v4.y;
                oacc[a][2] += p * v4.z; oacc[a][3] += p * v4.w;
            }
        }
    }
    #pragma unroll
    for (int a = 0; a < 4; a++) {
        int i = ti + 16 * a;
        float4 o4 = {oacc[a][0], oacc[a][1], oacc[a][2], oacc[a][3]};
        *(float4*)(O + ((size_t)(qt0 + i) * B_ + b) * D_ + h * DH + td * 4) = o4;
    }
}

#define QA_SMEM ((48 * 512 + 10 * 512 + 10 * 48 + 48) * 4)

// ---------------- host launcher ----------------
extern "C" void kernel_launch(void* const* d_in, const int* in_sizes, int n_in,
                              void* d_out, int out_size) {
    const float* tgt     = (const float*)d_in[0];
    const float* memory  = (const float*)d_in[1];
    const float* queries = (const float*)d_in[2];
    const float* wk      = (const float*)d_in[3];
    const float* in_w    = (const float*)d_in[4];
    const float* in_b    = (const float*)d_in[5];
    const float* out_w   = (const float*)d_in[6];
    const float* out_b   = (const float*)d_in[7];
    const float* l1w     = (const float*)d_in[8];
    const float* l1b     = (const float*)d_in[9];
    const float* l2w     = (const float*)d_in[10];
    const float* l2b     = (const float*)d_in[11];
    const float* ln1g    = (const float*)d_in[12];
    const float* ln1b    = (const float*)d_in[13];
    const float* ln2g    = (const float*)d_in[14];
    const float* ln2b    = (const float*)d_in[15];
    const float* ln3g    = (const float*)d_in[16];
    const float* ln3b    = (const float*)d_in[17];
    float* out = (float*)d_out;

    float *qa, *x1, *qb, *kv, *ob, *tmp, *x2, *hbuf;
    cudaGetSymbolAddress((void**)&qa,   g_qa);
    cudaGetSymbolAddress((void**)&x1,   g_x1);
    cudaGetSymbolAddress((void**)&qb,   g_q);
    cudaGetSymbolAddress((void**)&kv,   g_kv);
    cudaGetSymbolAddress((void**)&ob,   g_o);
    cudaGetSymbolAddress((void**)&tmp,  g_tmp);
    cudaGetSymbolAddress((void**)&x2,   g_x2);
    cudaGetSymbolAddress((void**)&hbuf, g_h);

    cudaFuncSetAttribute(qa_kernel,  cudaFuncAttributeMaxDynamicSharedMemorySize, QA_SMEM);
    cudaFuncSetAttribute(attn_kernel, cudaFuncAttributeMaxDynamicSharedMemorySize, ATTN_SMEM);

    const int MR = T_ * B_;   // 16384 rows

    // 1. QaN block + LN1
    prep_q_kernel<<<NQ_ * H_, 32>>>(queries);
    qa_kernel<<<B_ * NW, 256, QA_SMEM>>>(tgt, wk);
    add_ln_kernel<<<MR, 256>>>(tgt, qa, ln1g, ln1b, x1, 1);

    // 2. MHA: projections
    sgemm_nt<0><<<dim3(512 / 128, MR / 128), 256>>>(x1, in_w, in_b, qb, MR, 512, 512);
    sgemm_nt<0><<<dim3(1024 / 128, (S_ * B_) / 128), 256>>>(memory, in_w + 512 * 512,
                                                            in_b + 512, kv, S_ * B_, 1024, 512);
    // 3. attention
    attn_kernel<<<dim3(T_ / 64, H_, B_), 256, ATTN_SMEM>>>(qb, kv, ob);
    // 4. out proj + LN2
    sgemm_nt<0><<<dim3(512 / 128, MR / 128), 256>>>(ob, out_w, out_b, tmp, MR, 512, 512);
    add_ln_kernel<<<MR, 256>>>(x1, tmp, ln2g, ln2b, x2, 0);

    // 5. FFN + LN3
    sgemm_nt<1><<<dim3(DFF_ / 128, MR / 128), 256>>>(x2, l1w, l1b, hbuf, MR, DFF_, 512);
    sgemm_nt<0><<<dim3(512 / 128, MR / 128), 256>>>(hbuf, l2w, l2b, tmp, MR, 512, DFF_);
    add_ln_kernel<<<MR, 256>>>(x2, tmp, ln3g, ln3b, out, 0);
}

// round 3
// speedup vs baseline: 1.7462x; 1.7462x over previous
#include <cuda_runtime.h>
#include <cuda_bf16.h>
#include <math.h>
#include <stdint.h>

#define T_   2048
#define B_   8
#define S_   512
#define D_   512
#define H_   8
#define DH   64
#define DFF_ 2048
#define NQ_  10
#define W_   16
#define NW   128
#define EPS  1e-5f
#define NEGV -1e30f

// ---------------- scratch (no dynamic allocation allowed) ----------------
__device__ float g_qn[NQ_ * D_];
__device__ float g_qa[B_ * NW * D_];
__device__ float g_x1[T_ * B_ * D_];
__device__ float g_q [T_ * B_ * D_];
__device__ float g_kv[S_ * B_ * 2 * D_];
__device__ float g_tmp[T_ * B_ * D_];
__device__ float g_x2[T_ * B_ * D_];

__device__ __nv_bfloat16 g_x1h[T_ * B_ * D_], g_x1l[T_ * B_ * D_];
__device__ __nv_bfloat16 g_x2h[T_ * B_ * D_], g_x2l[T_ * B_ * D_];
__device__ __nv_bfloat16 g_obh[T_ * B_ * D_], g_obl[T_ * B_ * D_];
__device__ __nv_bfloat16 g_hh [T_ * B_ * DFF_], g_hl [T_ * B_ * DFF_];
__device__ __nv_bfloat16 g_memh[S_ * B_ * D_], g_meml[S_ * B_ * D_];
// weights: in (1536*512) | out (512*512) | l1 (2048*512) | l2 (512*2048)
#define WOFF_IN  0
#define WOFF_OUT (1536 * 512)
#define WOFF_L1  (WOFF_OUT + 512 * 512)
#define WOFF_L2  (WOFF_L1 + 2048 * 512)
#define WTOT     (WOFF_L2 + 512 * 2048)
__device__ __nv_bfloat16 g_wh[WTOT], g_wl[WTOT];

// ---------------- helpers ----------------
__device__ __forceinline__ uint32_t smem_u32(const void* p) {
    uint32_t a;
    asm("{ .reg .u64 t; cvta.to.shared.u64 t, %1; cvt.u32.u64 %0, t; }" : "=r"(a) : "l"(p));
    return a;
}

// split one fp32 into hi/lo bf16
__device__ __forceinline__ void split1(float a, __nv_bfloat16& h, __nv_bfloat16& l) {
    h = __float2bfloat16(a);
    l = __float2bfloat16(a - __bfloat162float(h));
}

__device__ __forceinline__ void ldsm4(uint32_t* r, uint32_t addr) {
    asm volatile("ldmatrix.sync.aligned.m8n8.x4.shared.b16 {%0,%1,%2,%3}, [%4];"
        : "=r"(r[0]), "=r"(r[1]), "=r"(r[2]), "=r"(r[3]) : "r"(addr));
}

__device__ __forceinline__ void mma_bf16(float* d, const uint32_t* a, uint32_t b0, uint32_t b1) {
    asm volatile("mma.sync.aligned.m16n8k16.row.col.f32.bf16.bf16.f32 "
        "{%0,%1,%2,%3}, {%4,%5,%6,%7}, {%8,%9}, {%0,%1,%2,%3};"
        : "+f"(d[0]), "+f"(d[1]), "+f"(d[2]), "+f"(d[3])
        : "r"(a[0]), "r"(a[1]), "r"(a[2]), "r"(a[3]), "r"(b0), "r"(b1));
}

// ---------------- fp32 -> bf16 hi/lo split (vectorized) ----------------
__global__ void split_kernel(const float4* __restrict__ src,
                             __nv_bfloat162* __restrict__ hi,
                             __nv_bfloat162* __restrict__ lo, int n4) {
    int i = blockIdx.x * 256 + threadIdx.x;
    if (i >= n4) return;
    float4 v = src[i];
    __nv_bfloat16 hx, lx, hy, ly, hz, lz, hw, lw;
    split1(v.x, hx, lx); split1(v.y, hy, ly);
    split1(v.z, hz, lz); split1(v.w, hw, lw);
    hi[2 * i]     = __nv_bfloat162(hx, hy);
    hi[2 * i + 1] = __nv_bfloat162(hz, hw);
    lo[2 * i]     = __nv_bfloat162(lx, ly);
    lo[2 * i + 1] = __nv_bfloat162(lz, lw);
}

// ================= HMMA GEMM: C[M,N] = A[M,K] @ W[N,K]^T + bias =================
// CTA 128x128, K-chunk 32, 8 warps (2x4), warp tile 64x32, split-bf16 (3 MMA).
// smem rows padded to 40 bf16 (80B = 20 banks) -> conflict-free ldmatrix.
template<int RELU, int OSPLIT>
__global__ __launch_bounds__(256, 2) void gemm_bf16(
    const __nv_bfloat16* __restrict__ Ah, const __nv_bfloat16* __restrict__ Al,
    const __nv_bfloat16* __restrict__ Bh, const __nv_bfloat16* __restrict__ Bl,
    const float* __restrict__ bias, float* __restrict__ C,
    __nv_bfloat16* __restrict__ Ch, __nv_bfloat16* __restrict__ Cl,
    int M, int N, int K)
{
    __shared__ __nv_bfloat16 sAh[128 * 40], sAl[128 * 40];
    __shared__ __nv_bfloat16 sBh[128 * 40], sBl[128 * 40];

    int tid = threadIdx.x, lane = tid & 31, wid = tid >> 5;
    int m0 = blockIdx.y * 128, n0 = blockIdx.x * 128;
    int warp_m = wid >> 2, warp_n = wid & 3;

    float acc[4][4][4];
    #pragma unroll
    for (int i = 0; i < 4; i++)
        #pragma unroll
        for (int j = 0; j < 4; j++)
            #pragma unroll
            for (int k = 0; k < 4; k++) acc[i][j][k] = 0.f;

    uint32_t uAh = smem_u32(sAh), uAl = smem_u32(sAl);
    uint32_t uBh = smem_u32(sBh), uBl = smem_u32(sBl);

    // ldmatrix lane offsets (bytes)
    uint32_t a_off = ((warp_m * 64 + (lane & 15)) * 40 + (lane >> 4) * 8) * 2;
    uint32_t b_off = ((warp_n * 32 + ((lane >> 4) & 1) * 8 + (lane & 7)) * 40
                      + ((lane >> 3) & 1) * 8) * 2;

    int lrow = tid >> 1;
    int lp   = (tid & 1) * 16;   // element offset 0 or 16
    uint32_t sdst = lrow * 40 + lp;

    for (int kc = 0; kc < K; kc += 32) {
        __syncthreads();
        {
            size_t ao = (size_t)(m0 + lrow) * K + kc + lp;
            size_t bo = (size_t)(n0 + lrow) * K + kc + lp;
            *(uint4*)&sAh[sdst]     = *(const uint4*)(Ah + ao);
            *(uint4*)&sAh[sdst + 8] = *(const uint4*)(Ah + ao + 8);
            *(uint4*)&sAl[sdst]     = *(const uint4*)(Al + ao);
            *(uint4*)&sAl[sdst + 8] = *(const uint4*)(Al + ao + 8);
            *(uint4*)&sBh[sdst]     = *(const uint4*)(Bh + bo);
            *(uint4*)&sBh[sdst + 8] = *(const uint4*)(Bh + bo + 8);
            *(uint4*)&sBl[sdst]     = *(const uint4*)(Bl + bo);
            *(uint4*)&sBl[sdst + 8] = *(const uint4*)(Bl + bo + 8);
        }
        __syncthreads();

        #pragma unroll
        for (int ks = 0; ks < 2; ks++) {
            uint32_t bh0[4], bh1[4], bl0[4], bl1[4];
            ldsm4(bh0, uBh + b_off + ks * 32);
            ldsm4(bh1, uBh + b_off + 1280 + ks * 32);
            ldsm4(bl0, uBl + b_off + ks * 32);
            ldsm4(bl1, uBl + b_off + 1280 + ks * 32);
            #pragma unroll
            for (int mi = 0; mi < 4; mi++) {
                uint32_t ah[4], al[4];
                ldsm4(ah, uAh + a_off + mi * 1280 + ks * 32);
                ldsm4(al, uAl + a_off + mi * 1280 + ks * 32);
                mma_bf16(acc[mi][0], ah, bh0[0], bh0[1]);
                mma_bf16(acc[mi][0], ah, bl0[0], bl0[1]);
                mma_bf16(acc[mi][0], al, bh0[0], bh0[1]);
                mma_bf16(acc[mi][1], ah, bh0[2], bh0[3]);
                mma_bf16(acc[mi][1], ah, bl0[2], bl0[3]);
                mma_bf16(acc[mi][1], al, bh0[2], bh0[3]);
                mma_bf16(acc[mi][2], ah, bh1[0], bh1[1]);
                mma_bf16(acc[mi][2], ah, bl1[0], bl1[1]);
                mma_bf16(acc[mi][2], al, bh1[0], bh1[1]);
                mma_bf16(acc[mi][3], ah, bh1[2], bh1[3]);
                mma_bf16(acc[mi][3], ah, bl1[2], bl1[3]);
                mma_bf16(acc[mi][3], al, bh1[2], bh1[3]);
            }
        }
    }

    // epilogue
    int r0 = lane >> 2, c0 = (lane & 3) * 2;
    int mbase = m0 + warp_m * 64, nbase = n0 + warp_n * 32;
    #pragma unroll
    for (int mi = 0; mi < 4; mi++) {
        #pragma unroll
        for (int nj = 0; nj < 4; nj++) {
            int nn = nbase + nj * 8 + c0;
            float b0 = bias[nn], b1 = bias[nn + 1];
            #pragma unroll
            for (int half = 0; half < 2; half++) {
                int mm = mbase + mi * 16 + r0 + half * 8;
                float v0 = acc[mi][nj][half * 2]     + b0;
                float v1 = acc[mi][nj][half * 2 + 1] + b1;
                if (RELU) { v0 = fmaxf(v0, 0.f); v1 = fmaxf(v1, 0.f); }
                size_t off = (size_t)mm * N + nn;
                if (OSPLIT) {
                    __nv_bfloat16 h0, l0, h1, l1;
                    split1(v0, h0, l0); split1(v1, h1, l1);
                    *(__nv_bfloat162*)(Ch + off) = __nv_bfloat162(h0, h1);
                    *(__nv_bfloat162*)(Cl + off) = __nv_bfloat162(l0, l1);
                } else {
                    *(float2*)(C + off) = make_float2(v0, v1);
                }
            }
        }
    }
}

// ---------------- query normalization (QaN) ----------------
__global__ void prep_q_kernel(const float* __restrict__ q) {
    int n = blockIdx.x / H_, h = blockIdx.x % H_;
    int lane = threadIdx.x;
    const float* base = q + n * D_ + h * DH;
    float v0 = base[lane];
    float v1 = base[lane + 32];
    float ss = v0 * v0 + v1 * v1;
    #pragma unroll
    for (int o = 16; o; o >>= 1) ss += __shfl_xor_sync(0xffffffffu, ss, o);
    float f = 1.0f / ((sqrtf(ss) + 1e-6f) * 8.0f * sqrtf(512.0f));
    g_qn[n * D_ + h * DH + lane]      = v0 * f;
    g_qn[n * D_ + h * DH + lane + 32] = v1 * f;
}

// ---------------- QaN local-attention block ----------------
__global__ __launch_bounds__(256) void qa_kernel(const float* __restrict__ tgt,
                                                 const float* __restrict__ wk) {
    extern __shared__ float sm[];
    float* kv  = sm;
    float* qs  = kv + 48 * 512;
    float* sim = qs + 10 * 512;
    float* wj  = sim + 10 * 48;

    int bx = blockIdx.x;
    int b = bx >> 7, m = bx & 127;
    int tid = threadIdx.x;

    for (int idx = tid; idx < 48 * 512; idx += 256) {
        int j = idx >> 9, d = idx & 511;
        int p = (m - 1) * W_ + j;
        kv[idx] = (p >= 0 && p < T_) ? tgt[(p * B_ + b) * D_ + d] : 0.0f;
    }
    for (int idx = tid; idx < 10 * 512; idx += 256) qs[idx] = g_qn[idx];
    __syncthreads();

    int w = tid >> 5, lane = tid & 31;
    for (int pw = w; pw < 480; pw += 8) {
        int n = pw / 48, j = pw % 48;
        const float* kr = kv + j * 512;
        const float* qr = qs + n * 512;
        float s = 0.f;
        for (int d = lane; d < 512; d += 32) s += kr[d] * qr[d];
        #pragma unroll
        for (int o = 16; o; o >>= 1) s += __shfl_xor_sync(0xffffffffu, s, o);
        if (lane == 0) {
            int win = m - 1 + (j >> 4);
            sim[n * 48 + j] = (win >= 0 && win < NW) ? s : NEGV;
        }
    }
    __syncthreads();

    for (int n = w; n < NQ_; n += 8) {
        float v0 = sim[n * 48 + lane];
        float v1 = (lane < 16) ? sim[n * 48 + 32 + lane] : NEGV;
        float mx = fmaxf(v0, v1);
        #pragma unroll
        for (int o = 16; o; o >>= 1) mx = fmaxf(mx, __shfl_xor_sync(0xffffffffu, mx, o));
        float e0 = __expf(v0 - mx);
        float e1 = (lane < 16) ? __expf(v1 - mx) : 0.f;
        float su = e0 + e1;
        #pragma unroll
        for (int o = 16; o; o >>= 1) su += __shfl_xor_sync(0xffffffffu, su, o);
        float inv = 1.0f / su;
        sim[n * 48 + lane] = e0 * inv;
        if (lane < 16) sim[n * 48 + 32 + lane] = e1 * inv;
    }
    __syncthreads();

    if (tid < 48) {
        float acc = 0.f;
        #pragma unroll
        for (int n = 0; n < NQ_; n++) acc += wk[n] * sim[n * 48 + tid];
        wj[tid] = acc;
    }
    __syncthreads();

    for (int d = tid; d < 512; d += 256) {
        float acc = 0.f;
        #pragma unroll
        for (int j = 0; j < 48; j++) acc += wj[j] * kv[j * 512 + d];
        g_qa[(b * NW + m) * D_ + d] = acc;
    }
}

// ---------------- residual add + LayerNorm (+ optional bf16 split out) ----------------
__device__ __forceinline__ float block_sum(float v, float* red) {
    int lane = threadIdx.x & 31, w = threadIdx.x >> 5;
    __syncthreads();
    #pragma unroll
    for (int o = 16; o; o >>= 1) v += __shfl_xor_sync(0xffffffffu, v, o);
    if (lane == 0) red[w] = v;
    __syncthreads();
    v = (lane < 8) ? red[lane] : 0.f;
    #pragma unroll
    for (int o = 4; o; o >>= 1) v += __shfl_xor_sync(0xffffffffu, v, o);
    return __shfl_sync(0xffffffffu, v, 0);
}

__global__ __launch_bounds__(256) void add_ln_kernel(const float* __restrict__ a,
                                                     const float* __restrict__ bsrc,
                                                     const float* __restrict__ g,
                                                     const float* __restrict__ be,
                                                     float* __restrict__ out,
                                                     __nv_bfloat16* __restrict__ oh,
                                                     __nv_bfloat16* __restrict__ ol,
                                                     int mode) {
    __shared__ float red[8];
    int r = blockIdx.x, tid = threadIdx.x;
    const float* ar = a + (size_t)r * D_;
    const float* br;
    if (mode == 1) {
        int t = r / B_, b = r % B_;
        br = bsrc + (size_t)(b * NW + (t >> 4)) * D_;
    } else {
        br = bsrc + (size_t)r * D_;
    }
    float x0 = ar[tid]       + br[tid];
    float x1 = ar[tid + 256] + br[tid + 256];
    float mu = block_sum(x0 + x1, red) * (1.0f / 512.0f);
    float d0 = x0 - mu, d1 = x1 - mu;
    float var = block_sum(d0 * d0 + d1 * d1, red) * (1.0f / 512.0f);
    float inv = rsqrtf(var + EPS);
    float y0 = d0 * inv * g[tid]       + be[tid];
    float y1 = d1 * inv * g[tid + 256] + be[tid + 256];
    size_t o0 = (size_t)r * D_ + tid, o1 = o0 + 256;
    out[o0] = y0;
    out[o1] = y1;
    if (oh) {
        __nv_bfloat16 h, l;
        split1(y0, h, l); oh[o0] = h; ol[o0] = l;
        split1(y1, h, l); oh[o1] = h; ol[o1] = l;
    }
}

// ---------------- cross attention (B,H) heads, S=512, dh=64 ----------------
#define SROW 513
#define ATTN_SMEM ((4096 + 8192 + 64 * SROW) * 4)

__global__ __launch_bounds__(256) void attn_kernel(const float* __restrict__ Q,
                                                   const float* __restrict__ KV,
                                                   __nv_bfloat16* __restrict__ Oh,
                                                   __nv_bfloat16* __restrict__ Ol) {
    extern __shared__ float sm[];
    float* Qt = sm;
    float* Kt = sm + 4096;
    float* Ss = Kt + 8192;

    int qt0 = blockIdx.x * 64, h = blockIdx.y, b = blockIdx.z;
    int tid = threadIdx.x;
    int ti = tid & 15, ts = tid >> 4;

    for (int idx = tid; idx < 4096; idx += 256) {
        int i = idx >> 6, d = idx & 63;
        Qt[d * 64 + i] = Q[((size_t)(qt0 + i) * B_ + b) * D_ + h * DH + d] * 0.125f;
    }

    for (int sch = 0; sch < 512; sch += 128) {
        __syncthreads();
        for (int idx = tid; idx < 8192; idx += 256) {
            int s = idx >> 6, d = idx & 63;
            Kt[d * 128 + s] = KV[((size_t)(sch + s) * B_ + b) * (2 * D_) + h * DH + d];
        }
        __syncthreads();
        float acc[4][8];
        #pragma unroll
        for (int a = 0; a < 4; a++)
            #pragma unroll
            for (int j = 0; j < 8; j++) acc[a][j] = 0.f;
        #pragma unroll 4
        for (int d = 0; d < 64; d++) {
            float4 q4 = *(const float4*)(Qt + d * 64 + ti * 4);
            float4 ka = *(const float4*)(Kt + d * 128 + ts * 8);
            float4 kb = *(const float4*)(Kt + d * 128 + ts * 8 + 4);
            float rq[4] = {q4.x, q4.y, q4.z, q4.w};
            float rk[8] = {ka.x, ka.y, ka.z, ka.w, kb.x, kb.y, kb.z, kb.w};
            #pragma unroll
            for (int a = 0; a < 4; a++)
                #pragma unroll
                for (int j = 0; j < 8; j++) acc[a][j] += rq[a] * rk[j];
        }
        #pragma unroll
        for (int a = 0; a < 4; a++)
            #pragma unroll
            for (int j = 0; j < 8; j++)
                Ss[(ti * 4 + a) * SROW + sch + ts * 8 + j] = acc[a][j];
    }
    __syncthreads();

    int w = tid >> 5, lane = tid & 31;
    for (int i = w * 8; i < w * 8 + 8; i++) {
        float* row = Ss + i * SROW;
        float mx = -INFINITY;
        for (int s = lane; s < 512; s += 32) mx = fmaxf(mx, row[s]);
        #pragma unroll
        for (int o = 16; o; o >>= 1) mx = fmaxf(mx, __shfl_xor_sync(0xffffffffu, mx, o));
        float su = 0.f;
        for (int s = lane; s < 512; s += 32) {
            float e = __expf(row[s] - mx);
            row[s] = e; su += e;
        }
        #pragma unroll
        for (int o = 16; o; o >>= 1) su += __shfl_xor_sync(0xffffffffu, su, o);
        float inv = 1.0f / su;
        for (int s = lane; s < 512; s += 32) row[s] *= inv;
    }

    float* Vs = Kt;
    int td = ts;
    float oacc[4][4];
    #pragma unroll
    for (int a = 0; a < 4; a++)
        #pragma unroll
        for (int j = 0; j < 4; j++) oacc[a][j] = 0.f;

    for (int sch = 0; sch < 512; sch += 64) {
        __syncthreads();
        for (int idx = tid; idx < 4096; idx += 256) {
            int s = idx >> 6, d = idx & 63;
            Vs[s * 68 + d] = KV[((size_t)(sch + s) * B_ + b) * (2 * D_) + D_ + h * DH + d];
        }
        __syncthreads();
        #pragma unroll 4
        for (int s = 0; s < 64; s++) {
            float4 v4 = *(const float4*)(Vs + s * 68 + td * 4);
            #pragma unroll
            for (int a = 0; a < 4; a++) {
                float p = Ss[(ti + 16 * a) * SROW + sch + s];
                oacc[a][0] += p * v4.x; oacc[a][1] += p * v4.y;
                oacc[a][2] += p * v4.z; oacc[a][3] += p * v4.w;
            }
        }
    }
    #pragma unroll
    for (int a = 0; a < 4; a++) {
        int i = ti + 16 * a;
        size_t base = ((size_t)(qt0 + i) * B_ + b) * D_ + h * DH + td * 4;
        __nv_bfloat16 h0, l0, h1, l1;
        split1(oacc[a][0], h0, l0); split1(oacc[a][1], h1, l1);
        *(__nv_bfloat162*)(Oh + base)     = __nv_bfloat162(h0, h1);
        *(__nv_bfloat162*)(Ol + base)     = __nv_bfloat162(l0, l1);
        split1(oacc[a][2], h0, l0); split1(oacc[a][3], h1, l1);
        *(__nv_bfloat162*)(Oh + base + 2) = __nv_bfloat162(h0, h1);
        *(__nv_bfloat162*)(Ol + base + 2) = __nv_bfloat162(l0, l1);
    }
}

#define QA_SMEM ((48 * 512 + 10 * 512 + 10 * 48 + 48) * 4)

// ---------------- host launcher ----------------
extern "C" void kernel_launch(void* const* d_in, const int* in_sizes, int n_in,
                              void* d_out, int out_size) {
    const float* tgt     = (const float*)d_in[0];
    const float* memory  = (const float*)d_in[1];
    const float* queries = (const float*)d_in[2];
    const float* wk      = (const float*)d_in[3];
    const float* in_w    = (const float*)d_in[4];
    const float* in_b    = (const float*)d_in[5];
    const float* out_w   = (const float*)d_in[6];
    const float* out_b   = (const float*)d_in[7];
    const float* l1w     = (const float*)d_in[8];
    const float* l1b     = (const float*)d_in[9];
    const float* l2w     = (const float*)d_in[10];
    const float* l2b     = (const float*)d_in[11];
    const float* ln1g    = (const float*)d_in[12];
    const float* ln1b    = (const float*)d_in[13];
    const float* ln2g    = (const float*)d_in[14];
    const float* ln2b    = (const float*)d_in[15];
    const float* ln3g    = (const float*)d_in[16];
    const float* ln3b    = (const float*)d_in[17];
    float* out = (float*)d_out;

    float *qa, *x1, *qb, *kv, *tmp, *x2;
    __nv_bfloat16 *x1h, *x1l, *x2h, *x2l, *obh, *obl, *hh, *hl, *memh, *meml, *wh, *wl;
    cudaGetSymbolAddress((void**)&qa,  g_qa);
    cudaGetSymbolAddress((void**)&x1,  g_x1);
    cudaGetSymbolAddress((void**)&qb,  g_q);
    cudaGetSymbolAddress((void**)&kv,  g_kv);
    cudaGetSymbolAddress((void**)&tmp, g_tmp);
    cudaGetSymbolAddress((void**)&x2,  g_x2);
    cudaGetSymbolAddress((void**)&x1h, g_x1h); cudaGetSymbolAddress((void**)&x1l, g_x1l);
    cudaGetSymbolAddress((void**)&x2h, g_x2h); cudaGetSymbolAddress((void**)&x2l, g_x2l);
    cudaGetSymbolAddress((void**)&obh, g_obh); cudaGetSymbolAddress((void**)&obl, g_obl);
    cudaGetSymbolAddress((void**)&hh,  g_hh);  cudaGetSymbolAddress((void**)&hl,  g_hl);
    cudaGetSymbolAddress((void**)&memh, g_memh); cudaGetSymbolAddress((void**)&meml, g_meml);
    cudaGetSymbolAddress((void**)&wh,  g_wh);  cudaGetSymbolAddress((void**)&wl,  g_wl);

    cudaFuncSetAttribute(qa_kernel,   cudaFuncAttributeMaxDynamicSharedMemorySize, QA_SMEM);
    cudaFuncSetAttribute(attn_kernel, cudaFuncAttributeMaxDynamicSharedMemorySize, ATTN_SMEM);

    const int MR = T_ * B_;   // 16384 rows

    // 0. split weights + memory into bf16 hi/lo
    auto splt = [&](const float* src, __nv_bfloat16* h, __nv_bfloat16* l, int n) {
        int n4 = n / 4;
        split_kernel<<<(n4 + 255) / 256, 256>>>((const float4*)src,
                                                (__nv_bfloat162*)h, (__nv_bfloat162*)l, n4);
    };
    splt(in_w,  wh + WOFF_IN,  wl + WOFF_IN,  1536 * 512);
    splt(out_w, wh + WOFF_OUT, wl + WOFF_OUT, 512 * 512);
    splt(l1w,   wh + WOFF_L1,  wl + WOFF_L1,  2048 * 512);
    splt(l2w,   wh + WOFF_L2,  wl + WOFF_L2,  512 * 2048);
    splt(memory, memh, meml, S_ * B_ * D_);

    // 1. QaN block + LN1
    prep_q_kernel<<<NQ_ * H_, 32>>>(queries);
    qa_kernel<<<B_ * NW, 256, QA_SMEM>>>(tgt, wk);
    add_ln_kernel<<<MR, 256>>>(tgt, qa, ln1g, ln1b, x1, x1h, x1l, 1);

    // 2. MHA projections (HMMA)
    gemm_bf16<0, 0><<<dim3(4, 128), 256>>>(x1h, x1l, wh + WOFF_IN, wl + WOFF_IN,
                                           in_b, qb, nullptr, nullptr, MR, 512, 512);
    gemm_bf16<0, 0><<<dim3(8, 32), 256>>>(memh, meml, wh + WOFF_IN + 512 * 512,
                                          wl + WOFF_IN + 512 * 512, in_b + 512,
                                          kv, nullptr, nullptr, S_ * B_, 1024, 512);
    // 3. attention (fp32, emits split bf16 output)
    attn_kernel<<<dim3(T_ / 64, H_, B_), 256, ATTN_SMEM>>>(qb, kv, obh, obl);
    // 4. out proj + LN2
    gemm_bf16<0, 0><<<dim3(4, 128), 256>>>(obh, obl, wh + WOFF_OUT, wl + WOFF_OUT,
                                           out_b, tmp, nullptr, nullptr, MR, 512, 512);
    add_ln_kernel<<<MR, 256>>>(x1, tmp, ln2g, ln2b, x2, x2h, x2l, 0);

    // 5. FFN + LN3
    gemm_bf16<1, 1><<<dim3(16, 128), 256>>>(x2h, x2l, wh + WOFF_L1, wl + WOFF_L1,
                                            l1b, nullptr, hh, hl, MR, DFF_, 512);
    gemm_bf16<0, 0><<<dim3(4, 128), 256>>>(hh, hl, wh + WOFF_L2, wl + WOFF_L2,
                                           l2b, tmp, nullptr, nullptr, MR, 512, DFF_);
    add_ln_kernel<<<MR, 256>>>(x2, tmp, ln3g, ln3b, out, nullptr, nullptr, 0);
}